// round 4
// baseline (speedup 1.0000x reference)
#include <cuda_runtime.h>
#include <cuda_bf16.h>
#include <cstdint>

#define DEVI __device__ __forceinline__

// ---------------------------------------------------------------------------
// Problem constants
// ---------------------------------------------------------------------------
namespace cfg {
constexpr int BROWS = 512;      // batch (GEMM M)
constexpr int DIM   = 512;      // embedding dim (GEMM K)
constexpr int NCLS  = 200000;   // classes (GEMM N, tiled)
constexpr int NT    = 128;      // classes per CTA
constexpr int GRIDN = (NCLS + NT - 1) / NT;   // 1563

// smem layout (bytes, within dynamic smem)
constexpr int SM_LAB  = 0;                    // 512 int32 labels
constexpr int SM_B    = 2048;                 // 8 K-slices x 128 rows x 128B
constexpr int SM_A    = SM_B + 131072;        // 2 buffers x 128 rows x 128B
constexpr int SM_TOT  = SM_A + 32768;         // 165888

constexpr float S_LOG2E = 92.33248261689366f; // 64 * log2(e)
}

// ---------------------------------------------------------------------------
// Device scratch (no allocations allowed)
// ---------------------------------------------------------------------------
__device__ __align__(16) float         g_en32[cfg::BROWS * cfg::DIM]; // norm emb fp32
__device__ __align__(16) __nv_bfloat16 g_en16[cfg::BROWS * cfg::DIM]; // norm emb bf16
__device__ float g_rowsum[cfg::BROWS];   // sum exp(l-64), excl target
__device__ float g_invn;                 // 1/n_valid

// ---------------------------------------------------------------------------
// PTX helpers (base-ISA only: legal on sm_103 / compute_103)
// ---------------------------------------------------------------------------
DEVI uint32_t smem_u32(const void* p) {
    uint32_t a;
    asm("{ .reg .u64 t; cvta.to.shared.u64 t, %1; cvt.u32.u64 %0, t; }"
        : "=r"(a) : "l"(p));
    return a;
}

DEVI float ex2_approx(float x) {
    float r;
    asm("ex2.approx.ftz.f32 %0, %1;" : "=f"(r) : "f"(x));
    return r;
}

DEVI void cp_async16(uint32_t dst, const void* src) {
    asm volatile("cp.async.cg.shared.global [%0], [%1], 16;"
                 :: "r"(dst), "l"(src) : "memory");
}
DEVI void cp_commit() { asm volatile("cp.async.commit_group;" ::: "memory"); }
template <int N> DEVI void cp_wait() {
    asm volatile("cp.async.wait_group %0;" :: "n"(N) : "memory");
}

DEVI void ldsm_x4(uint32_t& r0, uint32_t& r1, uint32_t& r2, uint32_t& r3,
                  uint32_t addr) {
    asm volatile("ldmatrix.sync.aligned.m8n8.x4.shared.b16 {%0,%1,%2,%3}, [%4];"
                 : "=r"(r0), "=r"(r1), "=r"(r2), "=r"(r3) : "r"(addr));
}

DEVI void mma16816(float* c, uint32_t a0, uint32_t a1, uint32_t a2, uint32_t a3,
                   uint32_t b0, uint32_t b1) {
    asm volatile(
        "mma.sync.aligned.m16n8k16.row.col.f32.bf16.bf16.f32 "
        "{%0,%1,%2,%3}, {%4,%5,%6,%7}, {%8,%9}, {%0,%1,%2,%3};"
        : "+f"(c[0]), "+f"(c[1]), "+f"(c[2]), "+f"(c[3])
        : "r"(a0), "r"(a1), "r"(a2), "r"(a3), "r"(b0), "r"(b1));
}

// ---------------------------------------------------------------------------
// Kernel 0: zero accumulators, count valid labels, zero output
// ---------------------------------------------------------------------------
__global__ void k0_prep(const int* __restrict__ labels,
                        float* __restrict__ out) {
    int t = threadIdx.x;
    g_rowsum[t] = 0.0f;
    int valid = (labels[t] >= 0) ? 1 : 0;
    int cnt = __syncthreads_count(valid);
    if (t == 0) {
        g_invn = 1.0f / fmaxf((float)cnt, 1.0f);
        out[0] = 0.0f;
    }
}

// ---------------------------------------------------------------------------
// Kernel 1: normalize embeddings -> fp32 + bf16 copies (warp per row)
// ---------------------------------------------------------------------------
__global__ void k1_norm(const float* __restrict__ emb) {
    int gw  = blockIdx.x * 8 + (threadIdx.x >> 5);
    int lid = threadIdx.x & 31;
    const float4* src = reinterpret_cast<const float4*>(emb) + (size_t)gw * 128;
    float4 v[4];
    float ss = 0.0f;
#pragma unroll
    for (int j = 0; j < 4; j++) {
        v[j] = src[j * 32 + lid];
        ss += v[j].x * v[j].x + v[j].y * v[j].y + v[j].z * v[j].z + v[j].w * v[j].w;
    }
#pragma unroll
    for (int s = 16; s > 0; s >>= 1) ss += __shfl_xor_sync(0xffffffffu, ss, s);
    float inv = 1.0f / fmaxf(sqrtf(ss), 1e-12f);

    float4* d32 = reinterpret_cast<float4*>(g_en32) + (size_t)gw * 128;
    uint2*  d16 = reinterpret_cast<uint2*>(g_en16) + (size_t)gw * 128;
#pragma unroll
    for (int j = 0; j < 4; j++) {
        float4 n = make_float4(v[j].x * inv, v[j].y * inv, v[j].z * inv, v[j].w * inv);
        d32[j * 32 + lid] = n;
        __nv_bfloat162 h0 = __float22bfloat162_rn(make_float2(n.x, n.y));
        __nv_bfloat162 h1 = __float22bfloat162_rn(make_float2(n.z, n.w));
        uint2 pk;
        pk.x = *reinterpret_cast<uint32_t*>(&h0);
        pk.y = *reinterpret_cast<uint32_t*>(&h1);
        d16[j * 32 + lid] = pk;
    }
}

// ---------------------------------------------------------------------------
// Kernel 2: fused bf16 mma.sync GEMM + softmax-denominator epilogue.
//
// Tile: CTA = 128 classes (N) x 512 batch (M) x 512 (K).
//   B (W tile, normalized bf16) lives in smem, K-slice-blocked:
//     byte = s*16384 + r*128 + ((c8 ^ (r&7))<<4)   (s: 64-K slice, r: class)
//   A (normalized embeddings) streamed as 128x64 slices via cp.async,
//     double-buffered, same per-row swizzle.
// 32 slices (4 M-chunks x 8 K-slices). After each M-chunk, fragment epilogue:
// clamp cos, ex2(64*log2e*(c-1)), mask target class, quad-reduce, atomicAdd.
// ---------------------------------------------------------------------------
__global__ void __launch_bounds__(256, 1)
k2_gemm(const float* __restrict__ W, const int* __restrict__ labels) {
    extern __shared__ __align__(1024) char smem[];
    const uint32_t sb = smem_u32(smem);
    const int tid = threadIdx.x;
    const int wid = tid >> 5;
    const int lid = tid & 31;
    const int wm  = wid & 3;        // warp M index (4 x 32 rows per chunk)
    const int wn  = wid >> 2;       // warp N index (2 x 64 classes)
    const int cls0 = blockIdx.x * cfg::NT;

    // labels -> smem (int32)
    int* slab = reinterpret_cast<int*>(smem + cfg::SM_LAB);
    slab[tid]       = labels[tid];
    slab[tid + 256] = labels[tid + 256];

    // ---- kick off A slice 0 (overlaps with W convert below) ----
    {
        const char* gsrc = reinterpret_cast<const char*>(g_en16);
#pragma unroll
        for (int q = 0; q < 4; q++) {
            int idx  = q * 256 + tid;          // 16B chunk id, 0..1023
            int row  = idx >> 3;               // 0..127
            int c8   = idx & 7;
            uint32_t dst = sb + cfg::SM_A + (uint32_t)row * 128
                         + (uint32_t)((c8 ^ (row & 7)) << 4);
            cp_async16(dst, gsrc + ((size_t)row * 512 + c8 * 8) * 2);
        }
        cp_commit();
    }

    // ---- Phase 1: W tile fp32 -> normalized bf16 into smem B ----
    for (int i = 0; i < 16; i++) {
        int r   = wid * 16 + i;                // class row within tile
        int cls = cls0 + r;
        float4 v[4];
        float  ss = 0.0f;
        if (cls < cfg::NCLS) {
            const float4* wr = reinterpret_cast<const float4*>(W) + (size_t)cls * 128;
#pragma unroll
            for (int j = 0; j < 4; j++) {
                v[j] = wr[j * 32 + lid];
                ss += v[j].x * v[j].x + v[j].y * v[j].y + v[j].z * v[j].z + v[j].w * v[j].w;
            }
        } else {
#pragma unroll
            for (int j = 0; j < 4; j++) v[j] = make_float4(0.f, 0.f, 0.f, 0.f);
        }
#pragma unroll
        for (int s = 16; s > 0; s >>= 1) ss += __shfl_xor_sync(0xffffffffu, ss, s);
        float inv = (cls < cfg::NCLS) ? 1.0f / fmaxf(sqrtf(ss), 1e-12f) : 0.0f;
#pragma unroll
        for (int j = 0; j < 4; j++) {
            float4 n = make_float4(v[j].x * inv, v[j].y * inv, v[j].z * inv, v[j].w * inv);
            __nv_bfloat162 h0 = __float22bfloat162_rn(make_float2(n.x, n.y));
            __nv_bfloat162 h1 = __float22bfloat162_rn(make_float2(n.z, n.w));
            uint2 pk;
            pk.x = *reinterpret_cast<uint32_t*>(&h0);
            pk.y = *reinterpret_cast<uint32_t*>(&h1);
            int k0  = (j * 32 + lid) * 4;      // element index 0..508
            int s4  = k0 >> 6;                 // K slice
            int k64 = k0 & 63;
            int c8  = k64 >> 3;
            uint32_t byte = (uint32_t)s4 * 16384 + (uint32_t)r * 128
                          + (uint32_t)((c8 ^ (r & 7)) << 4) + (uint32_t)((k64 & 7) * 2);
            *reinterpret_cast<uint2*>(smem + cfg::SM_B + byte) = pk;
        }
    }

    float acc[2][8][4];
#pragma unroll
    for (int a = 0; a < 2; a++)
#pragma unroll
        for (int b = 0; b < 8; b++)
#pragma unroll
            for (int c = 0; c < 4; c++) acc[a][b][c] = 0.0f;

    const int grp = lid >> 2;      // 0..7 (row within 8)
    const int qid = lid & 3;       // quad lane

    // ---- Mainloop: 32 slices ----
    for (int i = 0; i < 32; i++) {
        // issue cp.async for slice i+1 (its buffer was last read at slice
        // i-1; the trailing __syncthreads of iter i-1 freed it)
        if (i + 1 < 32) {
            int mc2 = (i + 1) >> 3, kk2 = (i + 1) & 7, bb = (i + 1) & 1;
            const char* gsrc = reinterpret_cast<const char*>(g_en16);
#pragma unroll
            for (int q = 0; q < 4; q++) {
                int idx  = q * 256 + tid;
                int row  = idx >> 3;
                int c8   = idx & 7;
                uint32_t dst = sb + cfg::SM_A + (uint32_t)bb * 16384
                             + (uint32_t)row * 128
                             + (uint32_t)((c8 ^ (row & 7)) << 4);
                size_t gofs = ((size_t)(mc2 * 128 + row) * 512 + kk2 * 64 + c8 * 8) * 2;
                cp_async16(dst, gsrc + gofs);
            }
            cp_commit();
            cp_wait<1>();          // slice i arrived
        } else {
            cp_wait<0>();
        }
        __syncthreads();           // slice i visible to all; B ready (iter 0)

        const uint32_t abase = sb + cfg::SM_A + (uint32_t)(i & 1) * 16384;
        const uint32_t bbase = sb + cfg::SM_B + (uint32_t)(i & 7) * 16384;

#pragma unroll
        for (int kt = 0; kt < 4; kt++) {
            // A fragments: 2 m-tiles of 16x16
            uint32_t af[2][4];
#pragma unroll
            for (int mt = 0; mt < 2; mt++) {
                int row = wm * 32 + mt * 16 + (lid & 15);
                int c8  = (kt * 2 + (lid >> 4)) ^ (row & 7);
                ldsm_x4(af[mt][0], af[mt][1], af[mt][2], af[mt][3],
                        abase + (uint32_t)row * 128 + (uint32_t)(c8 << 4));
            }
            // B fragments: 4 n-tile-pairs of (16 n x 16 k)
            uint32_t bf[4][4];
#pragma unroll
            for (int np = 0; np < 4; np++) {
                int n   = np * 16 + ((lid >> 4) << 3) + (lid & 7);
                int row = wn * 64 + n;
                int c8  = (kt * 2 + ((lid >> 3) & 1)) ^ (row & 7);
                ldsm_x4(bf[np][0], bf[np][1], bf[np][2], bf[np][3],
                        bbase + (uint32_t)row * 128 + (uint32_t)(c8 << 4));
            }
#pragma unroll
            for (int mt = 0; mt < 2; mt++)
#pragma unroll
                for (int np = 0; np < 4; np++) {
                    mma16816(acc[mt][np * 2],
                             af[mt][0], af[mt][1], af[mt][2], af[mt][3],
                             bf[np][0], bf[np][1]);
                    mma16816(acc[mt][np * 2 + 1],
                             af[mt][0], af[mt][1], af[mt][2], af[mt][3],
                             bf[np][2], bf[np][3]);
                }
        }
        __syncthreads();           // all reads of buf[i&1] done

        // ---- per-M-chunk epilogue ----
        if ((i & 7) == 7) {
            int mc = i >> 3;
            int row0 = mc * 128 + wm * 32 + grp;   // rows row0(+mt*16), +8
#pragma unroll
            for (int mt = 0; mt < 2; mt++) {
                int ra = row0 + mt * 16;
                int rb = ra + 8;
                int la = slab[ra];
                int lb = slab[rb];
                float sa = 0.0f, sbm = 0.0f;
#pragma unroll
                for (int nt = 0; nt < 8; nt++) {
                    int cbase = cls0 + wn * 64 + nt * 8 + qid * 2;
#pragma unroll
                    for (int h = 0; h < 2; h++) {
                        int cls = cbase + h;
                        bool oob = (cls >= cfg::NCLS);
                        float c0 = acc[mt][nt][h];
                        float c2 = acc[mt][nt][2 + h];
                        c0 = fminf(fmaxf(c0, -1.0f), 1.0f);
                        c2 = fminf(fmaxf(c2, -1.0f), 1.0f);
                        float e0 = ex2_approx(fmaf(c0, cfg::S_LOG2E, -cfg::S_LOG2E));
                        float e2 = ex2_approx(fmaf(c2, cfg::S_LOG2E, -cfg::S_LOG2E));
                        sa  += (oob || cls == la) ? 0.0f : e0;
                        sbm += (oob || cls == lb) ? 0.0f : e2;
                    }
                }
                sa  += __shfl_xor_sync(0xffffffffu, sa, 1);
                sa  += __shfl_xor_sync(0xffffffffu, sa, 2);
                sbm += __shfl_xor_sync(0xffffffffu, sbm, 1);
                sbm += __shfl_xor_sync(0xffffffffu, sbm, 2);
                if (qid == 0) {
                    atomicAdd(&g_rowsum[ra], sa);
                    atomicAdd(&g_rowsum[rb], sbm);
                }
            }
#pragma unroll
            for (int a = 0; a < 2; a++)
#pragma unroll
                for (int b = 0; b < 8; b++)
#pragma unroll
                    for (int c = 0; c < 4; c++) acc[a][b][c] = 0.0f;
        }
    }
}

// ---------------------------------------------------------------------------
// Kernel 3: finalize — exact fp32 target logit with arcface margin + loss
// ---------------------------------------------------------------------------
__global__ void k3_fin(const float* __restrict__ W,
                       const int* __restrict__ labels,
                       float* __restrict__ out) {
    int wid = threadIdx.x >> 5, lid = threadIdx.x & 31;
    int row = blockIdx.x * 8 + wid;
    int lb = labels[row];
    if (lb < 0) return;   // invalid row: excluded from mean

    const float4* er = reinterpret_cast<const float4*>(g_en32) + (size_t)row * 128;
    const float4* wr = reinterpret_cast<const float4*>(W) + (size_t)lb * 128;
    float dot = 0.0f, ww = 0.0f;
#pragma unroll
    for (int j = 0; j < 4; j++) {
        float4 e = er[j * 32 + lid];
        float4 w = wr[j * 32 + lid];
        dot += e.x * w.x + e.y * w.y + e.z * w.z + e.w * w.w;
        ww  += w.x * w.x + w.y * w.y + w.z * w.z + w.w * w.w;
    }
#pragma unroll
    for (int s = 16; s > 0; s >>= 1) {
        dot += __shfl_xor_sync(0xffffffffu, dot, s);
        ww  += __shfl_xor_sync(0xffffffffu, ww, s);
    }
    if (lid == 0) {
        float wn   = fmaxf(sqrtf(ww), 1e-12f);
        float cosr = dot / wn;
        float tgt  = fminf(fmaxf(cosr, -1.0f), 1.0f);
        float th   = acosf(fminf(fmaxf(tgt, -1.0f + 1e-7f), 1.0f - 1e-7f));
        float nt   = cosf(th + 0.5f);                       // cos(theta + m)
        float et   = exp2f(fmaf(nt, cfg::S_LOG2E, -cfg::S_LOG2E));
        float se   = g_rowsum[row] + et;                    // full shifted sum
        float nll  = 64.0f + logf(se) - 64.0f * nt;         // lse - target logit
        atomicAdd(out, nll * g_invn);
    }
}

// ---------------------------------------------------------------------------
// Launch
// ---------------------------------------------------------------------------
extern "C" void kernel_launch(void* const* d_in, const int* in_sizes, int n_in,
                              void* d_out, int out_size) {
    const float* emb    = (const float*)d_in[0];
    const int*   labels = (const int*)d_in[1];
    const float* W      = (const float*)d_in[2];
    float*       out    = (float*)d_out;

    cudaFuncSetAttribute(k2_gemm, cudaFuncAttributeMaxDynamicSharedMemorySize,
                         cfg::SM_TOT);

    k0_prep<<<1, 512>>>(labels, out);
    k1_norm<<<64, 256>>>(emb);
    k2_gemm<<<cfg::GRIDN, 256, cfg::SM_TOT>>>(W, labels);
    k3_fin<<<64, 256>>>(W, labels, out);
}

// round 5
// speedup vs baseline: 1.1705x; 1.1705x over previous
#include <cuda_runtime.h>
#include <cuda_bf16.h>
#include <cstdint>

#define DEVI __device__ __forceinline__

// ---------------------------------------------------------------------------
// Problem constants
// ---------------------------------------------------------------------------
namespace cfg {
constexpr int BROWS = 512;      // batch (GEMM M)
constexpr int DIM   = 512;      // embedding dim (GEMM K)
constexpr int NCLS  = 200000;   // classes (GEMM N, tiled)
constexpr int NT    = 128;      // classes per CTA
constexpr int GRIDN = (NCLS + NT - 1) / NT;   // 1563

// smem layout (bytes, within dynamic smem)
constexpr int SM_INV = 0;                     // 128 floats (1/||w|| per class)
constexpr int SM_B   = 1024;                  // 8 K-slices x 128 rows x 128B
constexpr int SM_A   = SM_B + 131072;         // 2 bufs x 128 rows x 128B
constexpr int SM_W   = SM_A + 32768;          // 2 bufs x 128 rows x 256B fp32
constexpr int SM_TOT = SM_W + 65536;          // 230400 (<= 227KB opt-in)

constexpr float S_LOG2E = 92.33248261689366f; // 64 * log2(e)
}

// ---------------------------------------------------------------------------
// Device scratch (no allocations allowed)
// ---------------------------------------------------------------------------
__device__ __align__(16) float         g_en32[cfg::BROWS * cfg::DIM]; // norm emb fp32
__device__ __align__(16) __nv_bfloat16 g_en16[cfg::BROWS * cfg::DIM]; // norm emb bf16
__device__ float g_rowsum[cfg::BROWS];   // sum exp(l-64), excl target
__device__ float g_invn;                 // 1/n_valid

// ---------------------------------------------------------------------------
// PTX helpers (base-ISA only: legal on sm_103 / compute_103)
// ---------------------------------------------------------------------------
DEVI uint32_t smem_u32(const void* p) {
    uint32_t a;
    asm("{ .reg .u64 t; cvta.to.shared.u64 t, %1; cvt.u32.u64 %0, t; }"
        : "=r"(a) : "l"(p));
    return a;
}

DEVI float ex2_approx(float x) {
    float r;
    asm("ex2.approx.ftz.f32 %0, %1;" : "=f"(r) : "f"(x));
    return r;
}

DEVI void cp_async16(uint32_t dst, const void* src) {
    asm volatile("cp.async.cg.shared.global [%0], [%1], 16;"
                 :: "r"(dst), "l"(src) : "memory");
}
// zero-fill variant: copies nbytes (0 or 16) from global, rest zero-filled
DEVI void cp_async16z(uint32_t dst, const void* src, uint32_t nbytes) {
    asm volatile("cp.async.cg.shared.global [%0], [%1], 16, %2;"
                 :: "r"(dst), "l"(src), "r"(nbytes) : "memory");
}
DEVI void cp_commit() { asm volatile("cp.async.commit_group;" ::: "memory"); }
template <int N> DEVI void cp_wait() {
    asm volatile("cp.async.wait_group %0;" :: "n"(N) : "memory");
}

DEVI void ldsm_x4(uint32_t& r0, uint32_t& r1, uint32_t& r2, uint32_t& r3,
                  uint32_t addr) {
    asm volatile("ldmatrix.sync.aligned.m8n8.x4.shared.b16 {%0,%1,%2,%3}, [%4];"
                 : "=r"(r0), "=r"(r1), "=r"(r2), "=r"(r3) : "r"(addr));
}

DEVI void mma16816(float* c, uint32_t a0, uint32_t a1, uint32_t a2, uint32_t a3,
                   uint32_t b0, uint32_t b1) {
    asm volatile(
        "mma.sync.aligned.m16n8k16.row.col.f32.bf16.bf16.f32 "
        "{%0,%1,%2,%3}, {%4,%5,%6,%7}, {%8,%9}, {%0,%1,%2,%3};"
        : "+f"(c[0]), "+f"(c[1]), "+f"(c[2]), "+f"(c[3])
        : "r"(a0), "r"(a1), "r"(a2), "r"(a3), "r"(b0), "r"(b1));
}

// ---------------------------------------------------------------------------
// Kernel 0: zero accumulators, count valid labels, zero output
// ---------------------------------------------------------------------------
__global__ void k0_prep(const int* __restrict__ labels,
                        float* __restrict__ out) {
    int t = threadIdx.x;
    g_rowsum[t] = 0.0f;
    int valid = (labels[t] >= 0) ? 1 : 0;
    int cnt = __syncthreads_count(valid);
    if (t == 0) {
        g_invn = 1.0f / fmaxf((float)cnt, 1.0f);
        out[0] = 0.0f;
    }
}

// ---------------------------------------------------------------------------
// Kernel 1: normalize embeddings -> fp32 + bf16 copies (warp per row)
// ---------------------------------------------------------------------------
__global__ void k1_norm(const float* __restrict__ emb) {
    int gw  = blockIdx.x * 8 + (threadIdx.x >> 5);
    int lid = threadIdx.x & 31;
    const float4* src = reinterpret_cast<const float4*>(emb) + (size_t)gw * 128;
    float4 v[4];
    float ss = 0.0f;
#pragma unroll
    for (int j = 0; j < 4; j++) {
        v[j] = src[j * 32 + lid];
        ss += v[j].x * v[j].x + v[j].y * v[j].y + v[j].z * v[j].z + v[j].w * v[j].w;
    }
#pragma unroll
    for (int s = 16; s > 0; s >>= 1) ss += __shfl_xor_sync(0xffffffffu, ss, s);
    float inv = 1.0f / fmaxf(sqrtf(ss), 1e-12f);

    float4* d32 = reinterpret_cast<float4*>(g_en32) + (size_t)gw * 128;
    uint2*  d16 = reinterpret_cast<uint2*>(g_en16) + (size_t)gw * 128;
#pragma unroll
    for (int j = 0; j < 4; j++) {
        float4 n = make_float4(v[j].x * inv, v[j].y * inv, v[j].z * inv, v[j].w * inv);
        d32[j * 32 + lid] = n;
        __nv_bfloat162 h0 = __float22bfloat162_rn(make_float2(n.x, n.y));
        __nv_bfloat162 h1 = __float22bfloat162_rn(make_float2(n.z, n.w));
        uint2 pk;
        pk.x = *reinterpret_cast<uint32_t*>(&h0);
        pk.y = *reinterpret_cast<uint32_t*>(&h1);
        d16[j * 32 + lid] = pk;
    }
}

// ---------------------------------------------------------------------------
// Kernel 2: fused bf16 mma.sync GEMM + softmax-denominator epilogue, with the
// W fp32->bf16 conversion pipelined into the first M-chunk.
//
//   B smem holds RAW bf16 W (unnormalized); per-class 1/||w|| moves to the
//   epilogue as a column scale (GEMM commutes with per-column scaling).
//   W slices (128 rows x 64 cols fp32 = 32KB) are staged via cp.async into a
//   double buffer in the SAME commit groups as the A slices, so W DRAM reads
//   overlap the m=0 MMAs. Sum-of-squares accumulates across slices; invw is
//   finalized at slice 7, right before the m=0 epilogue needs it.
// ---------------------------------------------------------------------------
__global__ void __launch_bounds__(256, 1)
k2_gemm(const float* __restrict__ W, const int* __restrict__ labels) {
    extern __shared__ __align__(1024) char smem[];
    const uint32_t sb = smem_u32(smem);
    const int tid = threadIdx.x;
    const int wid = tid >> 5;
    const int lid = tid & 31;
    const int wm  = wid & 3;        // warp M index (4 x 32 rows per chunk)
    const int wn  = wid >> 2;       // warp N index (2 x 64 classes)
    const int cls0 = blockIdx.x * cfg::NT;

    float* sinv = reinterpret_cast<float*>(smem + cfg::SM_INV);

    // ---- prologue: stage A slice 0 + W slice 0 (one commit group) ----
    {
        const char* gsrc = reinterpret_cast<const char*>(g_en16);
#pragma unroll
        for (int q = 0; q < 4; q++) {
            int idx = q * 256 + tid;           // 16B chunk id, 0..1023
            int row = idx >> 3, c8 = idx & 7;
            uint32_t dst = sb + cfg::SM_A + (uint32_t)row * 128
                         + (uint32_t)((c8 ^ (row & 7)) << 4);
            cp_async16(dst, gsrc + ((size_t)row * 512 + c8 * 8) * 2);
        }
#pragma unroll
        for (int q = 0; q < 8; q++) {
            int g = q * 256 + tid;             // 16B chunk id, 0..2047
            int row = g >> 4, c = g & 15;
            int cls = cls0 + row;
            bool ok = (cls < cfg::NCLS);
            uint32_t dst = sb + cfg::SM_W + (uint32_t)row * 256
                         + (uint32_t)((c ^ (row & 15)) << 4);
            const float* src = W + (size_t)(ok ? cls : 0) * 512 + c * 4;
            cp_async16z(dst, src, ok ? 16u : 0u);
        }
        cp_commit();
    }

    float wss = 0.0f;      // partial sum-sq: row tid>>1, col half tid&1
    float acc[2][8][4];
#pragma unroll
    for (int a = 0; a < 2; a++)
#pragma unroll
        for (int b = 0; b < 8; b++)
#pragma unroll
            for (int c = 0; c < 4; c++) acc[a][b][c] = 0.0f;

    const int grp = lid >> 2;      // 0..7 (row within 8)
    const int qid = lid & 3;       // quad lane

    // ---- Mainloop: 32 slices (4 M-chunks x 8 K-slices) ----
    for (int i = 0; i < 32; i++) {
        const int kc = i & 7;

        // issue commit group i: A slice i+1 (+ W slice i+1 while i<7)
        if (i + 1 < 32) {
            int mc2 = (i + 1) >> 3, kk2 = (i + 1) & 7, bb = (i + 1) & 1;
            const char* gsrc = reinterpret_cast<const char*>(g_en16);
#pragma unroll
            for (int q = 0; q < 4; q++) {
                int idx = q * 256 + tid;
                int row = idx >> 3, c8 = idx & 7;
                uint32_t dst = sb + cfg::SM_A + (uint32_t)bb * 16384
                             + (uint32_t)row * 128
                             + (uint32_t)((c8 ^ (row & 7)) << 4);
                size_t gofs = ((size_t)(mc2 * 128 + row) * 512 + kk2 * 64 + c8 * 8) * 2;
                cp_async16(dst, gsrc + gofs);
            }
            if (i < 7) {
                int ks = i + 1;
#pragma unroll
                for (int q = 0; q < 8; q++) {
                    int g = q * 256 + tid;
                    int row = g >> 4, c = g & 15;
                    int cls = cls0 + row;
                    bool ok = (cls < cfg::NCLS);
                    uint32_t dst = sb + cfg::SM_W + (uint32_t)(ks & 1) * 32768
                                 + (uint32_t)row * 256
                                 + (uint32_t)((c ^ (row & 15)) << 4);
                    const float* src = W + (size_t)(ok ? cls : 0) * 512 + ks * 64 + c * 4;
                    cp_async16z(dst, src, ok ? 16u : 0u);
                }
            }
            cp_commit();
            cp_wait<1>();          // group i-1 (A slice i, W slice i) arrived
        } else {
            cp_wait<0>();
        }
        __syncthreads();

        // ---- m=0 only: convert staged W slice kc -> B slice kc ----
        if (i < 8) {
            const int row = tid >> 1;
            const int hh  = tid & 1;
            const char* wbase = smem + cfg::SM_W + (size_t)(kc & 1) * 32768
                              + (size_t)row * 256;
            char* bbase = smem + cfg::SM_B + (size_t)kc * 16384 + (size_t)row * 128;
#pragma unroll
            for (int j = 0; j < 8; j++) {
                int c = hh * 8 + j;
                float4 v = *reinterpret_cast<const float4*>(
                    wbase + ((c ^ (row & 15)) << 4));
                wss += v.x * v.x + v.y * v.y + v.z * v.z + v.w * v.w;
                __nv_bfloat162 h0 = __float22bfloat162_rn(make_float2(v.x, v.y));
                __nv_bfloat162 h1 = __float22bfloat162_rn(make_float2(v.z, v.w));
                uint2 pk;
                pk.x = *reinterpret_cast<uint32_t*>(&h0);
                pk.y = *reinterpret_cast<uint32_t*>(&h1);
                *reinterpret_cast<uint2*>(
                    bbase + (((c >> 1) ^ (row & 7)) << 4) + (c & 1) * 8) = pk;
            }
            if (kc == 7) {
                float tot = wss + __shfl_xor_sync(0xffffffffu, wss, 1);
                if (hh == 0)
                    sinv[row] = 1.0f / fmaxf(sqrtf(tot), 1e-12f);
            }
            __syncthreads();       // B slice kc (and invw at kc=7) visible
        }

        const uint32_t abase = sb + cfg::SM_A + (uint32_t)(i & 1) * 16384;
        const uint32_t bbase = sb + cfg::SM_B + (uint32_t)kc * 16384;

#pragma unroll
        for (int kt = 0; kt < 4; kt++) {
            // A fragments: 2 m-tiles of 16x16
            uint32_t af[2][4];
#pragma unroll
            for (int mt = 0; mt < 2; mt++) {
                int row = wm * 32 + mt * 16 + (lid & 15);
                int c8  = (kt * 2 + (lid >> 4)) ^ (row & 7);
                ldsm_x4(af[mt][0], af[mt][1], af[mt][2], af[mt][3],
                        abase + (uint32_t)row * 128 + (uint32_t)(c8 << 4));
            }
            // B fragments: 4 n-tile-pairs of (16 n x 16 k)
            uint32_t bf[4][4];
#pragma unroll
            for (int np = 0; np < 4; np++) {
                int n   = np * 16 + ((lid >> 4) << 3) + (lid & 7);
                int row = wn * 64 + n;
                int c8  = (kt * 2 + ((lid >> 3) & 1)) ^ (row & 7);
                ldsm_x4(bf[np][0], bf[np][1], bf[np][2], bf[np][3],
                        bbase + (uint32_t)row * 128 + (uint32_t)(c8 << 4));
            }
#pragma unroll
            for (int mt = 0; mt < 2; mt++)
#pragma unroll
                for (int np = 0; np < 4; np++) {
                    mma16816(acc[mt][np * 2],
                             af[mt][0], af[mt][1], af[mt][2], af[mt][3],
                             bf[np][0], bf[np][1]);
                    mma16816(acc[mt][np * 2 + 1],
                             af[mt][0], af[mt][1], af[mt][2], af[mt][3],
                             bf[np][2], bf[np][3]);
                }
        }
        __syncthreads();           // all reads of A buf[i&1] done

        // ---- per-M-chunk epilogue ----
        if (kc == 7) {
            int mc = i >> 3;
            int row0 = mc * 128 + wm * 32 + grp;   // rows row0(+mt*16), +8
#pragma unroll
            for (int mt = 0; mt < 2; mt++) {
                int ra = row0 + mt * 16;
                int rb = ra + 8;
                int la  = labels[ra];
                int lbv = labels[rb];
                float sa = 0.0f, sbv = 0.0f;
#pragma unroll
                for (int nt = 0; nt < 8; nt++) {
                    int lc = wn * 64 + nt * 8 + qid * 2;
                    float2 iv = *reinterpret_cast<const float2*>(sinv + lc);
                    int cbase = cls0 + lc;
#pragma unroll
                    for (int h = 0; h < 2; h++) {
                        int cls = cbase + h;
                        float ivv = h ? iv.y : iv.x;
                        bool oob = (cls >= cfg::NCLS);
                        float c0 = acc[mt][nt][h]     * ivv;
                        float c2 = acc[mt][nt][2 + h] * ivv;
                        c0 = fminf(fmaxf(c0, -1.0f), 1.0f);
                        c2 = fminf(fmaxf(c2, -1.0f), 1.0f);
                        float e0 = ex2_approx(fmaf(c0, cfg::S_LOG2E, -cfg::S_LOG2E));
                        float e2 = ex2_approx(fmaf(c2, cfg::S_LOG2E, -cfg::S_LOG2E));
                        sa  += (oob || cls == la)  ? 0.0f : e0;
                        sbv += (oob || cls == lbv) ? 0.0f : e2;
                    }
                }
                sa  += __shfl_xor_sync(0xffffffffu, sa, 1);
                sa  += __shfl_xor_sync(0xffffffffu, sa, 2);
                sbv += __shfl_xor_sync(0xffffffffu, sbv, 1);
                sbv += __shfl_xor_sync(0xffffffffu, sbv, 2);
                if (qid == 0) {
                    atomicAdd(&g_rowsum[ra], sa);
                    atomicAdd(&g_rowsum[rb], sbv);
                }
            }
#pragma unroll
            for (int a = 0; a < 2; a++)
#pragma unroll
                for (int b = 0; b < 8; b++)
#pragma unroll
                    for (int c = 0; c < 4; c++) acc[a][b][c] = 0.0f;
        }
    }
}

// ---------------------------------------------------------------------------
// Kernel 3: finalize — exact fp32 target logit with arcface margin + loss
// ---------------------------------------------------------------------------
__global__ void k3_fin(const float* __restrict__ W,
                       const int* __restrict__ labels,
                       float* __restrict__ out) {
    int wid = threadIdx.x >> 5, lid = threadIdx.x & 31;
    int row = blockIdx.x * 8 + wid;
    int lb = labels[row];
    if (lb < 0) return;   // invalid row: excluded from mean

    const float4* er = reinterpret_cast<const float4*>(g_en32) + (size_t)row * 128;
    const float4* wr = reinterpret_cast<const float4*>(W) + (size_t)lb * 128;
    float dot = 0.0f, ww = 0.0f;
#pragma unroll
    for (int j = 0; j < 4; j++) {
        float4 e = er[j * 32 + lid];
        float4 w = wr[j * 32 + lid];
        dot += e.x * w.x + e.y * w.y + e.z * w.z + e.w * w.w;
        ww  += w.x * w.x + w.y * w.y + w.z * w.z + w.w * w.w;
    }
#pragma unroll
    for (int s = 16; s > 0; s >>= 1) {
        dot += __shfl_xor_sync(0xffffffffu, dot, s);
        ww  += __shfl_xor_sync(0xffffffffu, ww, s);
    }
    if (lid == 0) {
        float wn   = fmaxf(sqrtf(ww), 1e-12f);
        float cosr = dot / wn;
        float tgt  = fminf(fmaxf(cosr, -1.0f), 1.0f);
        float th   = acosf(fminf(fmaxf(tgt, -1.0f + 1e-7f), 1.0f - 1e-7f));
        float nt   = cosf(th + 0.5f);                       // cos(theta + m)
        float et   = exp2f(fmaf(nt, cfg::S_LOG2E, -cfg::S_LOG2E));
        float se   = g_rowsum[row] + et;                    // full shifted sum
        float nll  = 64.0f + logf(se) - 64.0f * nt;         // lse - target logit
        atomicAdd(out, nll * g_invn);
    }
}

// ---------------------------------------------------------------------------
// Launch
// ---------------------------------------------------------------------------
extern "C" void kernel_launch(void* const* d_in, const int* in_sizes, int n_in,
                              void* d_out, int out_size) {
    const float* emb    = (const float*)d_in[0];
    const int*   labels = (const int*)d_in[1];
    const float* W      = (const float*)d_in[2];
    float*       out    = (float*)d_out;

    cudaFuncSetAttribute(k2_gemm, cudaFuncAttributeMaxDynamicSharedMemorySize,
                         cfg::SM_TOT);

    k0_prep<<<1, 512>>>(labels, out);
    k1_norm<<<64, 256>>>(emb);
    k2_gemm<<<cfg::GRIDN, 256, cfg::SM_TOT>>>(W, labels);
    k3_fin<<<64, 256>>>(W, labels, out);
}